// round 2
// baseline (speedup 1.0000x reference)
#include <cuda_runtime.h>
#include <stdint.h>

#define NN 50000
#define EE 800000
#define EP (NN + EE)
#define DD 64
#define HH 4
#define CC 16
#define LL 3
#define SCAN_B 1024
#define NBLK ((NN + SCAN_B - 1) / SCAN_B)

typedef unsigned long long ull;

// ---------------- scratch (device globals: no allocation allowed) ----------------
__device__ __align__(16) float g_h[NN * DD];
__device__ __align__(16) float g_h0[NN * DD];
__device__ __align__(16) float g_xl[NN * DD];
__device__ __align__(16) float g_xr[NN * DD];
__device__ __align__(16) float g_res[NN * DD];
__device__ int g_deg[NN];
__device__ int g_scan[NN];
__device__ int g_rowptr[NN + 1];
__device__ int g_cursor[NN];
__device__ int g_col[EP];
__device__ int g_bsum[64];
__device__ int g_bsumex[64];

// packed fp32x2 FMA (SASS FFMA2) — 2x fp32 throughput, only reachable via PTX
__device__ __forceinline__ ull fma2(ull a, ull b, ull c) {
    ull d;
    asm("fma.rn.f32x2 %0, %1, %2, %3;" : "=l"(d) : "l"(a), "l"(b), "l"(c));
    return d;
}
__device__ __forceinline__ float hsum2(ull a) {
    float2 u = *(float2*)&a;
    return u.x + u.y;
}

// ---------------- input projection: h = relu(x@Wt+bt); h = [h, Et[type]]@Wp + bp ----------------
__global__ void k_input(const float* __restrict__ x, const int* __restrict__ node_type,
                        const float* __restrict__ Wt, const float* __restrict__ bt,
                        const float* __restrict__ Et, const float* __restrict__ Wp,
                        const float* __restrict__ bp) {
    __shared__ float tmp[4][DD];
    int nl = threadIdx.x >> 6;
    int c  = threadIdx.x & 63;
    int node = blockIdx.x * 4 + nl;
    float a = 0.f;
    if (node < NN) {
        a = bt[c];
        #pragma unroll
        for (int f = 0; f < 8; f++) a += x[node * 8 + f] * Wt[f * DD + c];
        tmp[nl][c] = fmaxf(a, 0.f);
    }
    __syncthreads();
    if (node < NN) {
        int t = node_type[node];
        float b = bp[c];
        #pragma unroll
        for (int k = 0; k < DD; k++) b += tmp[nl][k] * Wp[k * DD + c];
        #pragma unroll
        for (int j = 0; j < 16; j++) b += Et[t * 16 + j] * Wp[(DD + j) * DD + c];
        g_h[node * DD + c]  = b;
        g_h0[node * DD + c] = b;
    }
}

// ---------------- CSR build ----------------
__global__ void k_count(const int* __restrict__ edst) {
    int i = blockIdx.x * 256 + threadIdx.x;
    if (i < EE) atomicAdd(&g_deg[edst[i]], 1);
    else if (i < EP) atomicAdd(&g_deg[i - EE], 1);   // self loop
}
__global__ void k_scan1() {
    __shared__ int wsum[32];
    int i = blockIdx.x * SCAN_B + threadIdx.x;
    int lane = threadIdx.x & 31, w = threadIdx.x >> 5;
    int v = (i < NN) ? g_deg[i] : 0;
    int s = v;
    #pragma unroll
    for (int o = 1; o < 32; o <<= 1) {
        int t = __shfl_up_sync(0xffffffffu, s, o);
        if (lane >= o) s += t;
    }
    if (lane == 31) wsum[w] = s;
    __syncthreads();
    if (w == 0) {
        int ws = wsum[lane];
        #pragma unroll
        for (int o = 1; o < 32; o <<= 1) {
            int t = __shfl_up_sync(0xffffffffu, ws, o);
            if (lane >= o) ws += t;
        }
        wsum[lane] = ws;
        if (lane == 31) g_bsum[blockIdx.x] = ws;     // block total
    }
    __syncthreads();
    int add = (w > 0) ? wsum[w - 1] : 0;
    if (i < NN) g_scan[i] = s + add;                 // inclusive scan of g_deg
}
__global__ void k_scan2() {
    __shared__ int sm[64];
    int v = (threadIdx.x < NBLK) ? g_bsum[threadIdx.x] : 0;
    sm[threadIdx.x] = v;
    __syncthreads();
    for (int ofs = 1; ofs < 64; ofs <<= 1) {
        int t = (threadIdx.x >= ofs) ? sm[threadIdx.x - ofs] : 0;
        __syncthreads();
        sm[threadIdx.x] += t;
        __syncthreads();
    }
    g_bsumex[threadIdx.x] = sm[threadIdx.x] - v;     // exclusive
}
__global__ void k_scan3() {
    int i = blockIdx.x * 256 + threadIdx.x;
    if (i < NN) {
        int ex = g_scan[i] - g_deg[i] + g_bsumex[i / SCAN_B];
        g_rowptr[i] = ex;
        g_cursor[i] = ex;
    }
    if (i == 0) g_rowptr[NN] = EP;
}
__global__ void k_scatter(const int* __restrict__ esrc, const int* __restrict__ edst) {
    int i = blockIdx.x * 256 + threadIdx.x;
    if (i < EE) {
        int pos = atomicAdd(&g_cursor[edst[i]], 1);
        g_col[pos] = esrc[i];
    } else if (i < EP) {
        int n = i - EE;
        int pos = atomicAdd(&g_cursor[n], 1);
        g_col[pos] = n;
    }
}

// ---------------- fused 3x GEMM via packed FFMA2: xl,xr,res = h @ {Wl,Wr,Wres} + bias ----------------
#define GT 512
#define GTILE 64
#define WROW 66   // padded (even) row stride for transposed weights
#define GEMM_SMEM ((GTILE * 64 + 3 * 64 * WROW) * 4)

__global__ __launch_bounds__(GT) void k_gemm3(
        const float* __restrict__ Wl, const float* __restrict__ bl,
        const float* __restrict__ Wr, const float* __restrict__ br,
        const float* __restrict__ Ws, const float* __restrict__ bs) {
    extern __shared__ float sm[];
    float (*hs)[64]   = (float(*)[64])sm;                   // [64 nodes][64 k]
    float (*ws)[WROW] = (float(*)[WROW])(sm + GTILE * 64);  // [192 = 3*tc][k]

    int t = threadIdx.x;
    int base = blockIdx.x * GTILE;
    for (int i = t; i < GTILE * 64; i += GT) {
        int r = i >> 6, c = i & 63;
        int node = base + r;
        hs[r][c] = (node < NN) ? g_h[node * DD + c] : 0.f;
    }
    for (int i = t; i < 4096; i += GT) {                    // transpose-stage weights
        int k = i >> 6, c = i & 63;
        ws[c][k]       = Wl[i];
        ws[64 + c][k]  = Wr[i];
        ws[128 + c][k] = Ws[i];
    }
    __syncthreads();

    int tc = t & 63;
    int tn = t >> 6;                                        // 0..7
    ull aL[8] = {}, aR[8] = {}, aS[8] = {};
    const ull* wl2 = (const ull*)ws[tc];
    const ull* wr2 = (const ull*)ws[64 + tc];
    const ull* wv2 = (const ull*)ws[128 + tc];
    #pragma unroll 8
    for (int k2 = 0; k2 < 32; k2++) {
        ull l2 = wl2[k2], r2 = wr2[k2], s2 = wv2[k2];
        #pragma unroll
        for (int j = 0; j < 8; j++) {
            ull h2 = *(const ull*)&hs[tn + 8 * j][k2 * 2];
            aL[j] = fma2(h2, l2, aL[j]);
            aR[j] = fma2(h2, r2, aR[j]);
            aS[j] = fma2(h2, s2, aS[j]);
        }
    }
    float bL = bl[tc], bR = br[tc], bS = bs[tc];
    #pragma unroll
    for (int j = 0; j < 8; j++) {
        int node = base + tn + 8 * j;
        if (node < NN) {
            g_xl[node * DD + tc]  = hsum2(aL[j]) + bL;
            g_xr[node * DD + tc]  = hsum2(aR[j]) + bR;
            g_res[node * DD + tc] = hsum2(aS[j]) + bS;
        }
    }
}

// ---------------- GAT aggregation + residual + LayerNorm (warp per dst node) ----------------
__device__ __forceinline__ float dl4(float4 x, float4 r, float4 a) {
    float e, s;
    e = x.x + r.x; e = fmaxf(e, 0.2f * e); s  = e * a.x;
    e = x.y + r.y; e = fmaxf(e, 0.2f * e); s += e * a.y;
    e = x.z + r.z; e = fmaxf(e, 0.2f * e); s += e * a.z;
    e = x.w + r.w; e = fmaxf(e, 0.2f * e); s += e * a.w;
    return s;
}
__device__ __forceinline__ void sc4(float4& c, float f) { c.x *= f; c.y *= f; c.z *= f; c.w *= f; }
__device__ __forceinline__ void fma4(float4& c, float w, float4 x) {
    c.x += w * x.x; c.y += w * x.y; c.z += w * x.z; c.w += w * x.w;
}
__device__ __forceinline__ float4 wred4(float4 v) {
    #pragma unroll
    for (int o = 4; o < 32; o <<= 1) {
        v.x += __shfl_xor_sync(0xffffffffu, v.x, o);
        v.y += __shfl_xor_sync(0xffffffffu, v.y, o);
        v.z += __shfl_xor_sync(0xffffffffu, v.z, o);
        v.w += __shfl_xor_sync(0xffffffffu, v.w, o);
    }
    return v;
}

__global__ void k_gat(const float* __restrict__ att, const float* __restrict__ gamma,
                      const float* __restrict__ beta, const float* __restrict__ alpha_p) {
    __shared__ float sout[8][DD];
    int gw = (blockIdx.x * blockDim.x + threadIdx.x) >> 5;
    if (gw >= NN) return;
    int lane = threadIdx.x & 31;
    int wib  = threadIdx.x >> 5;
    int node = gw;
    int head = lane & 3;
    int el   = lane >> 2;
    const float NEG_INF = __int_as_float(0xff800000);

    const float4* xrp = (const float4*)(g_xr + node * DD + head * CC);
    float4 r0 = xrp[0], r1 = xrp[1], r2 = xrp[2], r3 = xrp[3];
    const float4* ap = (const float4*)(att + head * CC);
    float4 a0 = ap[0], a1 = ap[1], a2 = ap[2], a3 = ap[3];

    float m = NEG_INF, s = 0.f;
    float4 c0 = {0, 0, 0, 0}, c1 = c0, c2 = c0, c3 = c0;

    int beg = g_rowptr[node], end = g_rowptr[node + 1];
    for (int j = beg; j < end; j += 8) {
        int idx = j + el;
        bool v = idx < end;
        int src = v ? g_col[idx] : node;
        const float4* xp = (const float4*)(g_xl + src * DD + head * CC);
        float4 x0 = xp[0], x1 = xp[1], x2 = xp[2], x3 = xp[3];
        float p = dl4(x0, r0, a0) + dl4(x1, r1, a1) + dl4(x2, r2, a2) + dl4(x3, r3, a3);
        if (!v) p = NEG_INF;
        float bm = p;
        bm = fmaxf(bm, __shfl_xor_sync(0xffffffffu, bm, 4));
        bm = fmaxf(bm, __shfl_xor_sync(0xffffffffu, bm, 8));
        bm = fmaxf(bm, __shfl_xor_sync(0xffffffffu, bm, 16));
        if (bm > m) {
            float sc = __expf(m - bm);
            s *= sc;
            sc4(c0, sc); sc4(c1, sc); sc4(c2, sc); sc4(c3, sc);
            m = bm;
        }
        float w = __expf(p - m);
        s += w;
        fma4(c0, w, x0); fma4(c1, w, x1); fma4(c2, w, x2); fma4(c3, w, x3);
    }
    #pragma unroll
    for (int o = 4; o < 32; o <<= 1) s += __shfl_xor_sync(0xffffffffu, s, o);
    c0 = wred4(c0); c1 = wred4(c1); c2 = wred4(c2); c3 = wred4(c3);
    float inv = 1.f / (s + 1e-16f);

    if (el == 0) {
        float4* so = (float4*)&sout[wib][head * CC];
        so[0] = make_float4(c0.x * inv, c0.y * inv, c0.z * inv, c0.w * inv);
        so[1] = make_float4(c1.x * inv, c1.y * inv, c1.z * inv, c1.w * inv);
        so[2] = make_float4(c2.x * inv, c2.y * inv, c2.z * inv, c2.w * inv);
        so[3] = make_float4(c3.x * inv, c3.y * inv, c3.z * inv, c3.w * inv);
    }
    __syncwarp();

    float alpha = *alpha_p;
    int cch = lane * 2;
    float t0 = sout[wib][cch]     + g_res[node * DD + cch];
    float t1 = sout[wib][cch + 1] + g_res[node * DD + cch + 1];
    t0 = alpha * t0 + (1.f - alpha) * g_h0[node * DD + cch];
    t1 = alpha * t1 + (1.f - alpha) * g_h0[node * DD + cch + 1];
    float sum = t0 + t1;
    #pragma unroll
    for (int o = 1; o < 32; o <<= 1) sum += __shfl_xor_sync(0xffffffffu, sum, o);
    float mean = sum * (1.f / 64.f);
    float d0 = t0 - mean, d1 = t1 - mean;
    float vs = d0 * d0 + d1 * d1;
    #pragma unroll
    for (int o = 1; o < 32; o <<= 1) vs += __shfl_xor_sync(0xffffffffu, vs, o);
    float rstd = rsqrtf(vs * (1.f / 64.f) + 1e-5f);
    g_h[node * DD + cch]     = gamma[cch]     * d0 * rstd + beta[cch];
    g_h[node * DD + cch + 1] = gamma[cch + 1] * d1 * rstd + beta[cch + 1];
}

// ---------------- output head: sigmoid(relu(h@W1+b1)@W2+b2), warp per node ----------------
__global__ void k_head(const float* __restrict__ W1, const float* __restrict__ b1,
                       const float* __restrict__ W2, const float* __restrict__ b2,
                       float* __restrict__ out) {
    __shared__ float sh[8][DD];
    int gw = (blockIdx.x * blockDim.x + threadIdx.x) >> 5;
    if (gw >= NN) return;
    int lane = threadIdx.x & 31;
    int wib  = threadIdx.x >> 5;
    sh[wib][lane]      = g_h[gw * DD + lane];
    sh[wib][lane + 32] = g_h[gw * DD + lane + 32];
    __syncwarp();
    float z = b1[lane];
    #pragma unroll
    for (int k = 0; k < DD; k++) z += sh[wib][k] * W1[k * 32 + lane];
    z = fmaxf(z, 0.f);
    float ps = z * W2[lane];
    #pragma unroll
    for (int o = 1; o < 32; o <<= 1) ps += __shfl_xor_sync(0xffffffffu, ps, o);
    if (lane == 0) out[gw] = 1.f / (1.f + __expf(-(ps + b2[0])));
}

// ---------------- launch ----------------
extern "C" void kernel_launch(void* const* d_in, const int* in_sizes, int n_in,
                              void* d_out, int out_size) {
    const float* x         = (const float*)d_in[0];
    const int*   node_type = (const int*)d_in[1];
    const int*   esrc      = (const int*)d_in[2];
    const int*   edst      = (const int*)d_in[3];
    const float* Wt        = (const float*)d_in[4];
    const float* bt        = (const float*)d_in[5];
    const float* Et        = (const float*)d_in[6];
    const float* Wp        = (const float*)d_in[7];
    const float* bp        = (const float*)d_in[8];
    const float* Wl        = (const float*)d_in[9];
    const float* bl        = (const float*)d_in[10];
    const float* Wr        = (const float*)d_in[11];
    const float* br        = (const float*)d_in[12];
    const float* att       = (const float*)d_in[13];
    const float* Wres      = (const float*)d_in[14];
    const float* bconv     = (const float*)d_in[15];
    const float* gamma     = (const float*)d_in[16];
    const float* beta      = (const float*)d_in[17];
    const float* alpha     = (const float*)d_in[18];
    const float* W1        = (const float*)d_in[19];
    const float* b1        = (const float*)d_in[20];
    const float* W2        = (const float*)d_in[21];
    const float* b2        = (const float*)d_in[22];
    float* out = (float*)d_out;

    cudaFuncSetAttribute(k_gemm3, cudaFuncAttributeMaxDynamicSharedMemorySize, GEMM_SMEM);

    void* degp = nullptr;
    cudaGetSymbolAddress(&degp, g_deg);
    cudaMemsetAsync(degp, 0, NN * sizeof(int), 0);

    k_input<<<(NN + 3) / 4, 256>>>(x, node_type, Wt, bt, Et, Wp, bp);
    k_count<<<(EP + 255) / 256, 256>>>(edst);
    k_scan1<<<NBLK, SCAN_B>>>();
    k_scan2<<<1, 64>>>();
    k_scan3<<<(NN + 255) / 256, 256>>>();
    k_scatter<<<(EP + 255) / 256, 256>>>(esrc, edst);

    for (int l = 0; l < LL; l++) {
        k_gemm3<<<(NN + GTILE - 1) / GTILE, GT, GEMM_SMEM>>>(
            Wl + l * DD * DD, bl + l * DD,
            Wr + l * DD * DD, br + l * DD,
            Wres + l * DD * DD, bconv + l * DD);
        k_gat<<<(NN + 7) / 8, 256>>>(att + l * HH * CC, gamma + l * DD, beta + l * DD, alpha);
    }
    k_head<<<(NN + 7) / 8, 256>>>(W1, b1, W2, b2, out);
}

// round 4
// speedup vs baseline: 1.0988x; 1.0988x over previous
#include <cuda_runtime.h>
#include <stdint.h>

#define NN 50000
#define EE 800000
#define EP (NN + EE)
#define DD 64
#define HH 4
#define CC 16
#define LL 3
#define CSRB 148
#define CSRT 1024
#define CHUNK 338      // ceil(NN / CSRB)

// ---------------- scratch (device globals: no allocation allowed) ----------------
__device__ __align__(16) float g_h[NN * DD];
__device__ __align__(16) float g_h0[NN * DD];
__device__ __align__(16) float g_xl[NN * DD];
__device__ __align__(16) float g_xr[NN * DD];
__device__ __align__(16) float g_res[NN * DD];
__device__ int g_deg[NN];
__device__ int g_rowptr[NN + 1];
__device__ int g_cursor[NN];
__device__ int g_col[EP];
__device__ int g_bsum[CSRB];
__device__ int g_barc;   // zero-init; returns to 0 after each barrier
__device__ int g_gen;    // monotone generation counter (persists across replays)

// ---------------- persistent CSR builder: init + count + scan + scatter, 1 kernel ----------------
__device__ __forceinline__ int bscan1024(int v, int* wsum) {
    int lane = threadIdx.x & 31, w = threadIdx.x >> 5;
    int s = v;
    #pragma unroll
    for (int o = 1; o < 32; o <<= 1) {
        int t = __shfl_up_sync(0xffffffffu, s, o);
        if (lane >= o) s += t;
    }
    if (lane == 31) wsum[w] = s;
    __syncthreads();
    if (w == 0) {
        int ws = wsum[lane];
        #pragma unroll
        for (int o = 1; o < 32; o <<= 1) {
            int t = __shfl_up_sync(0xffffffffu, ws, o);
            if (lane >= o) ws += t;
        }
        wsum[lane] = ws;
    }
    __syncthreads();
    return s + ((w > 0) ? wsum[w - 1] : 0);
}

__global__ __launch_bounds__(CSRT) void k_csr(const int* __restrict__ esrc,
                                              const int* __restrict__ edst) {
    __shared__ int wsum[32];
    __shared__ int s_bs[CSRB];
    __shared__ int s_gen;
    int tid = threadIdx.x, b = blockIdx.x;
    const int stride = CSRB * CSRT;

    if (tid == 0) s_gen = atomicAdd(&g_gen, 0);   // all blocks read same base (no release yet)
    __syncthreads();

    // barrier as a lambda-style macro
#define GSYNC() do {                                                         \
        __syncthreads();                                                     \
        if (tid == 0) {                                                      \
            int tg = ++s_gen;                                                \
            __threadfence();                                                 \
            if (atomicAdd(&g_barc, 1) == CSRB - 1) {                         \
                atomicExch(&g_barc, 0);                                      \
                atomicExch(&g_gen, tg);                                      \
            } else {                                                         \
                while (atomicAdd(&g_gen, 0) < tg) { }                        \
            }                                                                \
        }                                                                    \
        __syncthreads();                                                     \
    } while (0)

    // phase A: degree init (self loop counts as 1)
    for (int i = b * CSRT + tid; i < NN; i += stride) g_deg[i] = 1;
    GSYNC();
    // phase B: count incoming edges
    for (int i = b * CSRT + tid; i < EE; i += stride) atomicAdd(&g_deg[edst[i]], 1);
    GSYNC();
    // phase C: per-block inclusive scan of this block's chunk
    int base = b * CHUNK;
    int n = NN - base; if (n > CHUNK) n = CHUNK;
    int idx = base + tid;
    int v = (tid < n) ? g_deg[idx] : 0;
    int incl = bscan1024(v, wsum);
    if (tid == CSRT - 1) g_bsum[b] = incl;        // block total
    GSYNC();
    // phase D: scan block totals (every block redundantly), write rowptr + cursor
    {
        int w2 = (tid < CSRB) ? g_bsum[tid] : 0;
        int incl2 = bscan1024(w2, wsum);
        if (tid < CSRB) s_bs[tid] = incl2;
        __syncthreads();
        int prefix = (b > 0) ? s_bs[b - 1] : 0;
        if (tid < n) {
            int ex = prefix + incl - v;
            g_rowptr[idx] = ex;
            g_cursor[idx] = ex;
        }
        if (b == 0 && tid == 0) g_rowptr[NN] = EP;
    }
    GSYNC();
    // phase E: scatter edges + self loops
    for (int i = b * CSRT + tid; i < EP; i += stride) {
        if (i < EE) {
            int pos = atomicAdd(&g_cursor[edst[i]], 1);
            g_col[pos] = esrc[i];
        } else {
            int nd = i - EE;
            int pos = atomicAdd(&g_cursor[nd], 1);
            g_col[pos] = nd;
        }
    }
#undef GSYNC
}

// ---------------- input projection: h = relu(x@Wt+bt); h = [h, Et[type]]@Wp + bp ----------------
__global__ void k_input(const float* __restrict__ x, const int* __restrict__ node_type,
                        const float* __restrict__ Wt, const float* __restrict__ bt,
                        const float* __restrict__ Et, const float* __restrict__ Wp,
                        const float* __restrict__ bp) {
    __shared__ float tmp[4][DD];
    int nl = threadIdx.x >> 6;
    int c  = threadIdx.x & 63;
    int node = blockIdx.x * 4 + nl;
    float a = 0.f;
    if (node < NN) {
        a = bt[c];
        #pragma unroll
        for (int f = 0; f < 8; f++) a += x[node * 8 + f] * Wt[f * DD + c];
        tmp[nl][c] = fmaxf(a, 0.f);
    }
    __syncthreads();
    if (node < NN) {
        int t = node_type[node];
        float b = bp[c];
        #pragma unroll
        for (int k = 0; k < DD; k++) b += tmp[nl][k] * Wp[k * DD + c];
        #pragma unroll
        for (int j = 0; j < 16; j++) b += Et[t * 16 + j] * Wp[(DD + j) * DD + c];
        g_h[node * DD + c]  = b;
        g_h0[node * DD + c] = b;
    }
}

// ---------------- fused 3x GEMM: xl = h@Wl+bl, xr = h@Wr+br, res = h@Wres+bconv ----------------
__global__ void k_gemm3(const float* __restrict__ Wl, const float* __restrict__ bl,
                        const float* __restrict__ Wr, const float* __restrict__ br,
                        const float* __restrict__ Ws, const float* __restrict__ bs) {
    __shared__ float hs[32][DD];
    int base = blockIdx.x * 32;
    int t = threadIdx.x;
    for (int i = t; i < 32 * DD; i += 256) {
        int r = i >> 6, c = i & 63;
        int node = base + r;
        hs[r][c] = (node < NN) ? g_h[node * DD + c] : 0.f;
    }
    __syncthreads();
    int tc = t & 63;
    int tn = t >> 6;  // 0..3
    float aL[8] = {}, aR[8] = {}, aS[8] = {};
    #pragma unroll 8
    for (int k = 0; k < DD; k++) {
        float wl = Wl[k * DD + tc], wr = Wr[k * DD + tc], ws = Ws[k * DD + tc];
        #pragma unroll
        for (int j = 0; j < 8; j++) {
            float hv = hs[tn + 4 * j][k];
            aL[j] += hv * wl; aR[j] += hv * wr; aS[j] += hv * ws;
        }
    }
    float bL = bl[tc], bR = br[tc], bS = bs[tc];
    #pragma unroll
    for (int j = 0; j < 8; j++) {
        int node = base + tn + 4 * j;
        if (node < NN) {
            g_xl[node * DD + tc]  = aL[j] + bL;
            g_xr[node * DD + tc]  = aR[j] + bR;
            g_res[node * DD + tc] = aS[j] + bS;
        }
    }
}

// ---------------- GAT aggregation + residual + LayerNorm (warp per dst node) ----------------
__device__ __forceinline__ float dl4(float4 x, float4 r, float4 a) {
    float e, s;
    e = x.x + r.x; e = fmaxf(e, 0.2f * e); s  = e * a.x;
    e = x.y + r.y; e = fmaxf(e, 0.2f * e); s += e * a.y;
    e = x.z + r.z; e = fmaxf(e, 0.2f * e); s += e * a.z;
    e = x.w + r.w; e = fmaxf(e, 0.2f * e); s += e * a.w;
    return s;
}
__device__ __forceinline__ void sc4(float4& c, float f) { c.x *= f; c.y *= f; c.z *= f; c.w *= f; }
__device__ __forceinline__ void fma4(float4& c, float w, float4 x) {
    c.x += w * x.x; c.y += w * x.y; c.z += w * x.z; c.w += w * x.w;
}
__device__ __forceinline__ float4 wred4(float4 v) {
    #pragma unroll
    for (int o = 4; o < 32; o <<= 1) {
        v.x += __shfl_xor_sync(0xffffffffu, v.x, o);
        v.y += __shfl_xor_sync(0xffffffffu, v.y, o);
        v.z += __shfl_xor_sync(0xffffffffu, v.z, o);
        v.w += __shfl_xor_sync(0xffffffffu, v.w, o);
    }
    return v;
}

template <bool LAST>
__global__ void k_gat(const float* __restrict__ att, const float* __restrict__ gamma,
                      const float* __restrict__ beta, const float* __restrict__ alpha_p,
                      const float* __restrict__ W1, const float* __restrict__ b1,
                      const float* __restrict__ W2, const float* __restrict__ b2,
                      float* __restrict__ out) {
    __shared__ float sout[8][DD];
    int gw = (blockIdx.x * blockDim.x + threadIdx.x) >> 5;
    if (gw >= NN) return;
    int lane = threadIdx.x & 31;
    int wib  = threadIdx.x >> 5;
    int node = gw;
    int head = lane & 3;
    int el   = lane >> 2;
    const float NEG_INF = __int_as_float(0xff800000);

    const float4* xrp = (const float4*)(g_xr + node * DD + head * CC);
    float4 r0 = xrp[0], r1 = xrp[1], r2 = xrp[2], r3 = xrp[3];
    const float4* ap = (const float4*)(att + head * CC);
    float4 a0 = ap[0], a1 = ap[1], a2 = ap[2], a3 = ap[3];

    float m = NEG_INF, s = 0.f;
    float4 c0 = {0, 0, 0, 0}, c1 = c0, c2 = c0, c3 = c0;

    int beg = g_rowptr[node], end = g_rowptr[node + 1];
    for (int j = beg; j < end; j += 8) {
        int idx = j + el;
        bool v = idx < end;
        int src = v ? g_col[idx] : node;
        const float4* xp = (const float4*)(g_xl + src * DD + head * CC);
        float4 x0 = xp[0], x1 = xp[1], x2 = xp[2], x3 = xp[3];
        float p = dl4(x0, r0, a0) + dl4(x1, r1, a1) + dl4(x2, r2, a2) + dl4(x3, r3, a3);
        if (!v) p = NEG_INF;
        float bm = p;
        bm = fmaxf(bm, __shfl_xor_sync(0xffffffffu, bm, 4));
        bm = fmaxf(bm, __shfl_xor_sync(0xffffffffu, bm, 8));
        bm = fmaxf(bm, __shfl_xor_sync(0xffffffffu, bm, 16));
        if (bm > m) {
            float sc = __expf(m - bm);
            s *= sc;
            sc4(c0, sc); sc4(c1, sc); sc4(c2, sc); sc4(c3, sc);
            m = bm;
        }
        float w = __expf(p - m);
        s += w;
        fma4(c0, w, x0); fma4(c1, w, x1); fma4(c2, w, x2); fma4(c3, w, x3);
    }
    #pragma unroll
    for (int o = 4; o < 32; o <<= 1) s += __shfl_xor_sync(0xffffffffu, s, o);
    c0 = wred4(c0); c1 = wred4(c1); c2 = wred4(c2); c3 = wred4(c3);
    float inv = 1.f / (s + 1e-16f);

    if (el == 0) {
        float4* so = (float4*)&sout[wib][head * CC];
        so[0] = make_float4(c0.x * inv, c0.y * inv, c0.z * inv, c0.w * inv);
        so[1] = make_float4(c1.x * inv, c1.y * inv, c1.z * inv, c1.w * inv);
        so[2] = make_float4(c2.x * inv, c2.y * inv, c2.z * inv, c2.w * inv);
        so[3] = make_float4(c3.x * inv, c3.y * inv, c3.z * inv, c3.w * inv);
    }
    __syncwarp();

    // residual + alpha blend + LayerNorm (2 channels per lane)
    float alpha = *alpha_p;
    int cch = lane * 2;
    float t0 = sout[wib][cch]     + g_res[node * DD + cch];
    float t1 = sout[wib][cch + 1] + g_res[node * DD + cch + 1];
    t0 = alpha * t0 + (1.f - alpha) * g_h0[node * DD + cch];
    t1 = alpha * t1 + (1.f - alpha) * g_h0[node * DD + cch + 1];
    float sum = t0 + t1;
    #pragma unroll
    for (int o = 1; o < 32; o <<= 1) sum += __shfl_xor_sync(0xffffffffu, sum, o);
    float mean = sum * (1.f / 64.f);
    float d0 = t0 - mean, d1 = t1 - mean;
    float vs = d0 * d0 + d1 * d1;
    #pragma unroll
    for (int o = 1; o < 32; o <<= 1) vs += __shfl_xor_sync(0xffffffffu, vs, o);
    float rstd = rsqrtf(vs * (1.f / 64.f) + 1e-5f);
    float h0v = gamma[cch]     * d0 * rstd + beta[cch];
    float h1v = gamma[cch + 1] * d1 * rstd + beta[cch + 1];

    if (!LAST) {
        g_h[node * DD + cch]     = h0v;
        g_h[node * DD + cch + 1] = h1v;
    } else {
        // fused output head: sigmoid(relu(h@W1+b1)@W2+b2)
        sout[wib][cch]     = h0v;
        sout[wib][cch + 1] = h1v;
        __syncwarp();
        float z = b1[lane];
        #pragma unroll
        for (int k = 0; k < DD; k++) z += sout[wib][k] * W1[k * 32 + lane];
        z = fmaxf(z, 0.f);
        float ps = z * W2[lane];
        #pragma unroll
        for (int o = 1; o < 32; o <<= 1) ps += __shfl_xor_sync(0xffffffffu, ps, o);
        if (lane == 0) out[node] = 1.f / (1.f + __expf(-(ps + b2[0])));
    }
}

// ---------------- launch ----------------
extern "C" void kernel_launch(void* const* d_in, const int* in_sizes, int n_in,
                              void* d_out, int out_size) {
    const float* x         = (const float*)d_in[0];
    const int*   node_type = (const int*)d_in[1];
    const int*   esrc      = (const int*)d_in[2];
    const int*   edst      = (const int*)d_in[3];
    const float* Wt        = (const float*)d_in[4];
    const float* bt        = (const float*)d_in[5];
    const float* Et        = (const float*)d_in[6];
    const float* Wp        = (const float*)d_in[7];
    const float* bp        = (const float*)d_in[8];
    const float* Wl        = (const float*)d_in[9];
    const float* bl        = (const float*)d_in[10];
    const float* Wr        = (const float*)d_in[11];
    const float* br        = (const float*)d_in[12];
    const float* att       = (const float*)d_in[13];
    const float* Wres      = (const float*)d_in[14];
    const float* bconv     = (const float*)d_in[15];
    const float* gamma     = (const float*)d_in[16];
    const float* beta      = (const float*)d_in[17];
    const float* alpha     = (const float*)d_in[18];
    const float* W1        = (const float*)d_in[19];
    const float* b1        = (const float*)d_in[20];
    const float* W2        = (const float*)d_in[21];
    const float* b2        = (const float*)d_in[22];
    float* out = (float*)d_out;

    // launch order chosen so ncu (-s 5) profiles k_gat layer 1
    k_csr<<<CSRB, CSRT>>>(esrc, edst);                                   // 0
    k_input<<<(NN + 3) / 4, 256>>>(x, node_type, Wt, bt, Et, Wp, bp);    // 1

    for (int l = 0; l < LL; l++) {
        k_gemm3<<<(NN + 31) / 32, 256>>>(Wl + l * DD * DD, bl + l * DD,  // 2,4,6
                                         Wr + l * DD * DD, br + l * DD,
                                         Wres + l * DD * DD, bconv + l * DD);
        if (l < LL - 1)
            k_gat<false><<<(NN + 7) / 8, 256>>>(att + l * HH * CC,       // 3,5
                gamma + l * DD, beta + l * DD, alpha,
                nullptr, nullptr, nullptr, nullptr, nullptr);
        else
            k_gat<true><<<(NN + 7) / 8, 256>>>(att + l * HH * CC,       // 7
                gamma + l * DD, beta + l * DD, alpha,
                W1, b1, W2, b2, out);
    }
}

// round 9
// speedup vs baseline: 1.3804x; 1.2562x over previous
#include <cuda_runtime.h>
#include <stdint.h>

#define NN 50000
#define EE 800000
#define EP (NN + EE)
#define DD 64
#define HH 4
#define CC 16
#define LL 3
#define CSRB 148
#define CSRT 1024
#define CHUNK 338      // ceil(NN / CSRB)

// ---------------- scratch (device globals: no allocation allowed) ----------------
__device__ __align__(16) float g_h[NN * DD];
__device__ __align__(16) float g_h0[NN * DD];
__device__ __align__(16) float g_xl[NN * DD];
__device__ __align__(16) float g_xr[NN * DD];
__device__ __align__(16) float g_res[NN * DD];
__device__ int g_deg[NN];
__device__ int g_rowptr[NN + 1];
__device__ int g_cursor[NN];
__device__ int g_col[EP];
__device__ int g_bsum[CSRB];
__device__ int g_barc;   // zero-init; returns to 0 after each barrier
__device__ int g_gen;    // monotone generation counter (persists across replays)

// ---------------- persistent CSR builder ----------------
__device__ __forceinline__ int bscan1024(int v, int* wsum) {
    int lane = threadIdx.x & 31, w = threadIdx.x >> 5;
    int s = v;
    #pragma unroll
    for (int o = 1; o < 32; o <<= 1) {
        int t = __shfl_up_sync(0xffffffffu, s, o);
        if (lane >= o) s += t;
    }
    if (lane == 31) wsum[w] = s;
    __syncthreads();
    if (w == 0) {
        int ws = wsum[lane];
        #pragma unroll
        for (int o = 1; o < 32; o <<= 1) {
            int t = __shfl_up_sync(0xffffffffu, ws, o);
            if (lane >= o) ws += t;
        }
        wsum[lane] = ws;
    }
    __syncthreads();
    return s + ((w > 0) ? wsum[w - 1] : 0);
}

__global__ __launch_bounds__(CSRT) void k_csr(const int* __restrict__ esrc,
                                              const int* __restrict__ edst) {
    __shared__ int wsum[32];
    __shared__ int s_bs[CSRB];
    __shared__ int s_gen;
    int tid = threadIdx.x, b = blockIdx.x;
    const int stride = CSRB * CSRT;

    if (tid == 0) s_gen = atomicAdd(&g_gen, 0);
    __syncthreads();

#define GSYNC() do {                                                         \
        __syncthreads();                                                     \
        if (tid == 0) {                                                      \
            int tg = ++s_gen;                                                \
            __threadfence();                                                 \
            if (atomicAdd(&g_barc, 1) == CSRB - 1) {                         \
                atomicExch(&g_barc, 0);                                      \
                atomicExch(&g_gen, tg);                                      \
            } else {                                                         \
                while (atomicAdd(&g_gen, 0) < tg) { }                        \
            }                                                                \
        }                                                                    \
        __syncthreads();                                                     \
    } while (0)

    for (int i = b * CSRT + tid; i < NN; i += stride) g_deg[i] = 1;
    GSYNC();
    for (int i = b * CSRT + tid; i < EE; i += stride) atomicAdd(&g_deg[edst[i]], 1);
    GSYNC();
    int base = b * CHUNK;
    int n = NN - base; if (n > CHUNK) n = CHUNK;
    int idx = base + tid;
    int v = (tid < n) ? g_deg[idx] : 0;
    int incl = bscan1024(v, wsum);
    if (tid == CSRT - 1) g_bsum[b] = incl;
    GSYNC();
    {
        int w2 = (tid < CSRB) ? g_bsum[tid] : 0;
        int incl2 = bscan1024(w2, wsum);
        if (tid < CSRB) s_bs[tid] = incl2;
        __syncthreads();
        int prefix = (b > 0) ? s_bs[b - 1] : 0;
        if (tid < n) {
            int ex = prefix + incl - v;
            g_rowptr[idx] = ex;
            g_cursor[idx] = ex;
        }
        if (b == 0 && tid == 0) g_rowptr[NN] = EP;
    }
    GSYNC();
    for (int i = b * CSRT + tid; i < EP; i += stride) {
        if (i < EE) {
            int pos = atomicAdd(&g_cursor[edst[i]], 1);
            g_col[pos] = esrc[i];
        } else {
            int nd = i - EE;
            int pos = atomicAdd(&g_cursor[nd], 1);
            g_col[pos] = nd;
        }
    }
#undef GSYNC
}

// ---------------- input projection ----------------
__global__ void k_input(const float* __restrict__ x, const int* __restrict__ node_type,
                        const float* __restrict__ Wt, const float* __restrict__ bt,
                        const float* __restrict__ Et, const float* __restrict__ Wp,
                        const float* __restrict__ bp) {
    __shared__ float tmp[4][DD];
    int nl = threadIdx.x >> 6;
    int c  = threadIdx.x & 63;
    int node = blockIdx.x * 4 + nl;
    float a = 0.f;
    if (node < NN) {
        a = bt[c];
        #pragma unroll
        for (int f = 0; f < 8; f++) a += x[node * 8 + f] * Wt[f * DD + c];
        tmp[nl][c] = fmaxf(a, 0.f);
    }
    __syncthreads();
    if (node < NN) {
        int t = node_type[node];
        float b = bp[c];
        #pragma unroll
        for (int k = 0; k < DD; k++) b += tmp[nl][k] * Wp[k * DD + c];
        #pragma unroll
        for (int j = 0; j < 16; j++) b += Et[t * 16 + j] * Wp[(DD + j) * DD + c];
        g_h[node * DD + c]  = b;
        g_h0[node * DD + c] = b;
    }
}

// ---------------- fused 3x GEMM ----------------
__global__ void k_gemm3(const float* __restrict__ Wl, const float* __restrict__ bl,
                        const float* __restrict__ Wr, const float* __restrict__ br,
                        const float* __restrict__ Ws, const float* __restrict__ bs) {
    __shared__ float hs[32][DD];
    int base = blockIdx.x * 32;
    int t = threadIdx.x;
    for (int i = t; i < 32 * DD; i += 256) {
        int r = i >> 6, c = i & 63;
        int node = base + r;
        hs[r][c] = (node < NN) ? g_h[node * DD + c] : 0.f;
    }
    __syncthreads();
    int tc = t & 63;
    int tn = t >> 6;
    float aL[8] = {}, aR[8] = {}, aS[8] = {};
    #pragma unroll 8
    for (int k = 0; k < DD; k++) {
        float wl = Wl[k * DD + tc], wr = Wr[k * DD + tc], ws = Ws[k * DD + tc];
        #pragma unroll
        for (int j = 0; j < 8; j++) {
            float hv = hs[tn + 4 * j][k];
            aL[j] += hv * wl; aR[j] += hv * wr; aS[j] += hv * ws;
        }
    }
    float bL = bl[tc], bR = br[tc], bS = bs[tc];
    #pragma unroll
    for (int j = 0; j < 8; j++) {
        int node = base + tn + 4 * j;
        if (node < NN) {
            g_xl[node * DD + tc]  = aL[j] + bL;
            g_xr[node * DD + tc]  = aR[j] + bR;
            g_res[node * DD + tc] = aS[j] + bS;
        }
    }
}

// ---------------- GAT aggregation (coalesced-row lane layout) ----------------
// lane = eg*16 + head*4 + quad.  Each LDG.128 reads 2 complete rows (contiguous).
__device__ __forceinline__ float dl4(float4 x, float4 r, float4 a) {
    float e, s;
    e = x.x + r.x; e = fmaxf(e, 0.2f * e); s  = e * a.x;
    e = x.y + r.y; e = fmaxf(e, 0.2f * e); s += e * a.y;
    e = x.z + r.z; e = fmaxf(e, 0.2f * e); s += e * a.z;
    e = x.w + r.w; e = fmaxf(e, 0.2f * e); s += e * a.w;
    return s;
}

template <bool LAST>
__global__ void __launch_bounds__(256) k_gat(
        const float* __restrict__ att, const float* __restrict__ gamma,
        const float* __restrict__ beta, const float* __restrict__ alpha_p,
        const float* __restrict__ W1, const float* __restrict__ b1,
        const float* __restrict__ W2, const float* __restrict__ b2,
        float* __restrict__ out) {
    __shared__ float sout[8][DD];
    int gw = (blockIdx.x * blockDim.x + threadIdx.x) >> 5;
    if (gw >= NN) return;
    int lane = threadIdx.x & 31;
    int wib  = threadIdx.x >> 5;
    int node = gw;
    int eg   = lane >> 4;        // edge group 0/1
    int hq   = lane & 15;        // head*4 + quad
    const float NEG_INF = __int_as_float(0xff800000);

    float4 r = *(const float4*)(g_xr + node * DD + hq * 4);
    float4 a = *(const float4*)(att + hq * 4);

    float m = NEG_INF, s = 0.f;
    float4 c = {0.f, 0.f, 0.f, 0.f};

    int beg = g_rowptr[node], end = g_rowptr[node + 1];
    for (int j = beg; j < end; j += 8) {
        float4 x0, x1, x2, x3;
        float p0, p1, p2, p3;
        {
            int i0 = j + eg,     i1 = j + 2 + eg, i2 = j + 4 + eg, i3 = j + 6 + eg;
            bool v0 = i0 < end,  v1 = i1 < end,   v2 = i2 < end,   v3 = i3 < end;
            int s0 = v0 ? g_col[i0] : node;
            int s1 = v1 ? g_col[i1] : node;
            int s2 = v2 ? g_col[i2] : node;
            int s3 = v3 ? g_col[i3] : node;
            x0 = *(const float4*)(g_xl + s0 * DD + hq * 4);
            x1 = *(const float4*)(g_xl + s1 * DD + hq * 4);
            x2 = *(const float4*)(g_xl + s2 * DD + hq * 4);
            x3 = *(const float4*)(g_xl + s3 * DD + hq * 4);
            p0 = v0 ? dl4(x0, r, a) : NEG_INF;
            p1 = v1 ? dl4(x1, r, a) : NEG_INF;
            p2 = v2 ? dl4(x2, r, a) : NEG_INF;
            p3 = v3 ? dl4(x3, r, a) : NEG_INF;
        }
        #pragma unroll
        for (int i = 0; i < 4; i++) {
            float sc = (i == 0) ? p0 : (i == 1) ? p1 : (i == 2) ? p2 : p3;
            float4 x = (i == 0) ? x0 : (i == 1) ? x1 : (i == 2) ? x2 : x3;
            // sum partial scores over the 4 quad lanes of this head
            sc += __shfl_xor_sync(0xffffffffu, sc, 1);
            sc += __shfl_xor_sync(0xffffffffu, sc, 2);
            // running max over both edge groups (uniform per head)
            float bm = fmaxf(sc, __shfl_xor_sync(0xffffffffu, sc, 16));
            if (bm > m) {
                float f = __expf(m - bm);
                s *= f; c.x *= f; c.y *= f; c.z *= f; c.w *= f;
                m = bm;
            }
            float w = __expf(sc - m);      // invalid -> exp(-inf - finite) = 0
            s += w;
            c.x += w * x.x; c.y += w * x.y; c.z += w * x.z; c.w += w * x.w;
        }
    }
    // combine the two edge groups
    s   += __shfl_xor_sync(0xffffffffu, s, 16);
    c.x += __shfl_xor_sync(0xffffffffu, c.x, 16);
    c.y += __shfl_xor_sync(0xffffffffu, c.y, 16);
    c.z += __shfl_xor_sync(0xffffffffu, c.z, 16);
    c.w += __shfl_xor_sync(0xffffffffu, c.w, 16);
    float inv = 1.f / (s + 1e-16f);

    if (eg == 0) {
        *(float4*)&sout[wib][hq * 4] =
            make_float4(c.x * inv, c.y * inv, c.z * inv, c.w * inv);
    }
    __syncwarp();

    // residual + alpha blend + LayerNorm (2 channels per lane)
    float alpha = *alpha_p;
    int cch = lane * 2;
    float t0 = sout[wib][cch]     + g_res[node * DD + cch];
    float t1 = sout[wib][cch + 1] + g_res[node * DD + cch + 1];
    t0 = alpha * t0 + (1.f - alpha) * g_h0[node * DD + cch];
    t1 = alpha * t1 + (1.f - alpha) * g_h0[node * DD + cch + 1];
    float sum = t0 + t1;
    #pragma unroll
    for (int o = 1; o < 32; o <<= 1) sum += __shfl_xor_sync(0xffffffffu, sum, o);
    float mean = sum * (1.f / 64.f);
    float d0 = t0 - mean, d1 = t1 - mean;
    float vs = d0 * d0 + d1 * d1;
    #pragma unroll
    for (int o = 1; o < 32; o <<= 1) vs += __shfl_xor_sync(0xffffffffu, vs, o);
    float rstd = rsqrtf(vs * (1.f / 64.f) + 1e-5f);
    float h0v = gamma[cch]     * d0 * rstd + beta[cch];
    float h1v = gamma[cch + 1] * d1 * rstd + beta[cch + 1];

    if (!LAST) {
        g_h[node * DD + cch]     = h0v;
        g_h[node * DD + cch + 1] = h1v;
    } else {
        sout[wib][cch]     = h0v;
        sout[wib][cch + 1] = h1v;
        __syncwarp();
        float z = b1[lane];
        #pragma unroll
        for (int k = 0; k < DD; k++) z += sout[wib][k] * W1[k * 32 + lane];
        z = fmaxf(z, 0.f);
        float ps = z * W2[lane];
        #pragma unroll
        for (int o = 1; o < 32; o <<= 1) ps += __shfl_xor_sync(0xffffffffu, ps, o);
        if (lane == 0) out[node] = 1.f / (1.f + __expf(-(ps + b2[0])));
    }
}

// ---------------- launch ----------------
extern "C" void kernel_launch(void* const* d_in, const int* in_sizes, int n_in,
                              void* d_out, int out_size) {
    const float* x         = (const float*)d_in[0];
    const int*   node_type = (const int*)d_in[1];
    const int*   esrc      = (const int*)d_in[2];
    const int*   edst      = (const int*)d_in[3];
    const float* Wt        = (const float*)d_in[4];
    const float* bt        = (const float*)d_in[5];
    const float* Et        = (const float*)d_in[6];
    const float* Wp        = (const float*)d_in[7];
    const float* bp        = (const float*)d_in[8];
    const float* Wl        = (const float*)d_in[9];
    const float* bl        = (const float*)d_in[10];
    const float* Wr        = (const float*)d_in[11];
    const float* br        = (const float*)d_in[12];
    const float* att       = (const float*)d_in[13];
    const float* Wres      = (const float*)d_in[14];
    const float* bconv     = (const float*)d_in[15];
    const float* gamma     = (const float*)d_in[16];
    const float* beta      = (const float*)d_in[17];
    const float* alpha     = (const float*)d_in[18];
    const float* W1        = (const float*)d_in[19];
    const float* b1        = (const float*)d_in[20];
    const float* W2        = (const float*)d_in[21];
    const float* b2        = (const float*)d_in[22];
    float* out = (float*)d_out;

    // launch order chosen so ncu (-s 5) profiles k_gat layer 2
    k_csr<<<CSRB, CSRT>>>(esrc, edst);                                   // 0
    k_input<<<(NN + 3) / 4, 256>>>(x, node_type, Wt, bt, Et, Wp, bp);    // 1

    for (int l = 0; l < LL; l++) {
        k_gemm3<<<(NN + 31) / 32, 256>>>(Wl + l * DD * DD, bl + l * DD,  // 2,4,6
                                         Wr + l * DD * DD, br + l * DD,
                                         Wres + l * DD * DD, bconv + l * DD);
        if (l < LL - 1)
            k_gat<false><<<(NN + 7) / 8, 256>>>(att + l * HH * CC,       // 3,5
                gamma + l * DD, beta + l * DD, alpha,
                nullptr, nullptr, nullptr, nullptr, nullptr);
        else
            k_gat<true><<<(NN + 7) / 8, 256>>>(att + l * HH * CC,       // 7
                gamma + l * DD, beta + l * DD, alpha,
                W1, b1, W2, b2, out);
    }
}

// round 10
// speedup vs baseline: 1.5587x; 1.1292x over previous
#include <cuda_runtime.h>
#include <stdint.h>

#define NN 50000
#define EE 800000
#define EP (NN + EE)
#define DD 64
#define HH 4
#define CC 16
#define LL 3
#define CSRB 148
#define CSRT 1024
#define CHUNK 338      // ceil(NN / CSRB)

typedef unsigned long long ull;

// ---------------- scratch (device globals: no allocation allowed) ----------------
__device__ __align__(16) float g_h[NN * DD];
__device__ __align__(16) float g_h0[NN * DD];
__device__ __align__(16) float g_xl[NN * DD];
__device__ __align__(16) float g_xr[NN * DD];
__device__ __align__(16) float g_res[NN * DD];
__device__ int g_deg[NN];
__device__ int g_rowptr[NN + 1];
__device__ int g_cursor[NN];
__device__ int g_col[EP];
__device__ int g_bsum[CSRB];
__device__ int g_barc;
__device__ int g_gen;

// packed fp32x2 FMA (SASS FFMA2): each half is an independent fp32 FMA
__device__ __forceinline__ ull fma2(ull a, ull b, ull c) {
    ull d;
    asm("fma.rn.f32x2 %0, %1, %2, %3;" : "=l"(d) : "l"(a), "l"(b), "l"(c));
    return d;
}

// ---------------- persistent CSR builder ----------------
__device__ __forceinline__ int bscan1024(int v, int* wsum) {
    int lane = threadIdx.x & 31, w = threadIdx.x >> 5;
    int s = v;
    #pragma unroll
    for (int o = 1; o < 32; o <<= 1) {
        int t = __shfl_up_sync(0xffffffffu, s, o);
        if (lane >= o) s += t;
    }
    if (lane == 31) wsum[w] = s;
    __syncthreads();
    if (w == 0) {
        int ws = wsum[lane];
        #pragma unroll
        for (int o = 1; o < 32; o <<= 1) {
            int t = __shfl_up_sync(0xffffffffu, ws, o);
            if (lane >= o) ws += t;
        }
        wsum[lane] = ws;
    }
    __syncthreads();
    return s + ((w > 0) ? wsum[w - 1] : 0);
}

__global__ __launch_bounds__(CSRT) void k_csr(const int* __restrict__ esrc,
                                              const int* __restrict__ edst) {
    __shared__ int wsum[32];
    __shared__ int s_bs[CSRB];
    __shared__ int s_gen;
    int tid = threadIdx.x, b = blockIdx.x;
    const int stride = CSRB * CSRT;

    if (tid == 0) s_gen = atomicAdd(&g_gen, 0);
    __syncthreads();

#define GSYNC() do {                                                         \
        __syncthreads();                                                     \
        if (tid == 0) {                                                      \
            int tg = ++s_gen;                                                \
            __threadfence();                                                 \
            if (atomicAdd(&g_barc, 1) == CSRB - 1) {                         \
                atomicExch(&g_barc, 0);                                      \
                atomicExch(&g_gen, tg);                                      \
            } else {                                                         \
                while (atomicAdd(&g_gen, 0) < tg) { }                        \
            }                                                                \
        }                                                                    \
        __syncthreads();                                                     \
    } while (0)

    for (int i = b * CSRT + tid; i < NN; i += stride) g_deg[i] = 1;
    GSYNC();
    for (int i = b * CSRT + tid; i < EE; i += stride) atomicAdd(&g_deg[edst[i]], 1);
    GSYNC();
    int base = b * CHUNK;
    int n = NN - base; if (n > CHUNK) n = CHUNK;
    int idx = base + tid;
    int v = (tid < n) ? g_deg[idx] : 0;
    int incl = bscan1024(v, wsum);
    if (tid == CSRT - 1) g_bsum[b] = incl;
    GSYNC();
    {
        int w2 = (tid < CSRB) ? g_bsum[tid] : 0;
        int incl2 = bscan1024(w2, wsum);
        if (tid < CSRB) s_bs[tid] = incl2;
        __syncthreads();
        int prefix = (b > 0) ? s_bs[b - 1] : 0;
        if (tid < n) {
            int ex = prefix + incl - v;
            g_rowptr[idx] = ex;
            g_cursor[idx] = ex;
        }
        if (b == 0 && tid == 0) g_rowptr[NN] = EP;
    }
    GSYNC();
    for (int i = b * CSRT + tid; i < EP; i += stride) {
        if (i < EE) {
            int pos = atomicAdd(&g_cursor[edst[i]], 1);
            g_col[pos] = esrc[i];
        } else {
            int nd = i - EE;
            int pos = atomicAdd(&g_cursor[nd], 1);
            g_col[pos] = nd;
        }
    }
#undef GSYNC
}

// ---------------- input projection ----------------
__global__ void k_input(const float* __restrict__ x, const int* __restrict__ node_type,
                        const float* __restrict__ Wt, const float* __restrict__ bt,
                        const float* __restrict__ Et, const float* __restrict__ Wp,
                        const float* __restrict__ bp) {
    __shared__ float tmp[4][DD];
    int nl = threadIdx.x >> 6;
    int c  = threadIdx.x & 63;
    int node = blockIdx.x * 4 + nl;
    float a = 0.f;
    if (node < NN) {
        a = bt[c];
        #pragma unroll
        for (int f = 0; f < 8; f++) a += x[node * 8 + f] * Wt[f * DD + c];
        tmp[nl][c] = fmaxf(a, 0.f);
    }
    __syncthreads();
    if (node < NN) {
        int t = node_type[node];
        float b = bp[c];
        #pragma unroll
        for (int k = 0; k < DD; k++) b += tmp[nl][k] * Wp[k * DD + c];
        #pragma unroll
        for (int j = 0; j < 16; j++) b += Et[t * 16 + j] * Wp[(DD + j) * DD + c];
        g_h[node * DD + c]  = b;
        g_h0[node * DD + c] = b;
    }
}

// ---------------- fused 3x GEMM via column-pair FFMA2 ----------------
// thread -> column pair (2*tc2, 2*tc2+1) x 8 nodes; each packed acc half is a full column sum
#define GTB 256
__global__ void __launch_bounds__(GTB) k_gemm3(
        const float* __restrict__ Wl, const float* __restrict__ bl,
        const float* __restrict__ Wr, const float* __restrict__ br,
        const float* __restrict__ Ws, const float* __restrict__ bs) {
    __shared__ float hs[64][DD];
    int base = blockIdx.x * 64;
    int t = threadIdx.x;
    for (int i = t; i < 64 * DD / 4; i += GTB) {
        int r = i >> 4, c4 = i & 15;
        int node = base + r;
        float4 v = (node < NN) ? *(const float4*)(g_h + node * DD + c4 * 4)
                               : make_float4(0.f, 0.f, 0.f, 0.f);
        *(float4*)&hs[r][c4 * 4] = v;
    }
    __syncthreads();
    int tc2 = t & 31;       // column pair index (lane)
    int tn  = t >> 5;       // node sub-group (warp-uniform)
    const ull* WlP = (const ull*)Wl + tc2;
    const ull* WrP = (const ull*)Wr + tc2;
    const ull* WsP = (const ull*)Ws + tc2;
    ull aL[8] = {}, aR[8] = {}, aS[8] = {};
    #pragma unroll 4
    for (int k2 = 0; k2 < 32; k2++) {
        ull wl0 = WlP[(2 * k2) * 32], wl1 = WlP[(2 * k2 + 1) * 32];
        ull wr0 = WrP[(2 * k2) * 32], wr1 = WrP[(2 * k2 + 1) * 32];
        ull ws0 = WsP[(2 * k2) * 32], ws1 = WsP[(2 * k2 + 1) * 32];
        #pragma unroll
        for (int j = 0; j < 8; j++) {
            float2 hv = *(const float2*)&hs[tn + 8 * j][2 * k2];   // warp-uniform broadcast
            ull h2a, h2b;
            asm("mov.b64 %0, {%1, %1};" : "=l"(h2a) : "f"(hv.x));
            asm("mov.b64 %0, {%1, %1};" : "=l"(h2b) : "f"(hv.y));
            aL[j] = fma2(h2a, wl0, aL[j]); aL[j] = fma2(h2b, wl1, aL[j]);
            aR[j] = fma2(h2a, wr0, aR[j]); aR[j] = fma2(h2b, wr1, aR[j]);
            aS[j] = fma2(h2a, ws0, aS[j]); aS[j] = fma2(h2b, ws1, aS[j]);
        }
    }
    float2 bL = *(const float2*)&bl[2 * tc2];
    float2 bR = *(const float2*)&br[2 * tc2];
    float2 bS = *(const float2*)&bs[2 * tc2];
    #pragma unroll
    for (int j = 0; j < 8; j++) {
        int node = base + tn + 8 * j;
        if (node < NN) {
            float2 l = *(float2*)&aL[j]; l.x += bL.x; l.y += bL.y;
            *(float2*)(g_xl + node * DD + 2 * tc2) = l;
            float2 r = *(float2*)&aR[j]; r.x += bR.x; r.y += bR.y;
            *(float2*)(g_xr + node * DD + 2 * tc2) = r;
            float2 sv = *(float2*)&aS[j]; sv.x += bS.x; sv.y += bS.y;
            *(float2*)(g_res + node * DD + 2 * tc2) = sv;
        }
    }
}

// ---------------- GAT aggregation (coalesced rows, batched max update) ----------------
__device__ __forceinline__ float dl4(float4 x, float4 r, float4 a) {
    float e, s;
    e = x.x + r.x; e = fmaxf(e, 0.2f * e); s  = e * a.x;
    e = x.y + r.y; e = fmaxf(e, 0.2f * e); s += e * a.y;
    e = x.z + r.z; e = fmaxf(e, 0.2f * e); s += e * a.z;
    e = x.w + r.w; e = fmaxf(e, 0.2f * e); s += e * a.w;
    return s;
}

template <bool LAST>
__global__ void __launch_bounds__(256) k_gat(
        const float* __restrict__ att, const float* __restrict__ gamma,
        const float* __restrict__ beta, const float* __restrict__ alpha_p,
        const float* __restrict__ W1, const float* __restrict__ b1,
        const float* __restrict__ W2, const float* __restrict__ b2,
        float* __restrict__ out) {
    __shared__ float sout[8][DD];
    int gw = (blockIdx.x * blockDim.x + threadIdx.x) >> 5;
    if (gw >= NN) return;
    int lane = threadIdx.x & 31;
    int wib  = threadIdx.x >> 5;
    int node = gw;
    int eg   = lane >> 4;
    int hq   = lane & 15;
    const float NEG_INF = __int_as_float(0xff800000);

    float4 r = *(const float4*)(g_xr + node * DD + hq * 4);
    float4 a = *(const float4*)(att + hq * 4);

    float m = NEG_INF, s = 0.f;
    float4 c = {0.f, 0.f, 0.f, 0.f};

    int beg = g_rowptr[node], end = g_rowptr[node + 1];
    for (int j = beg; j < end; j += 8) {
        int i0 = j + eg, i1 = j + 2 + eg, i2 = j + 4 + eg, i3 = j + 6 + eg;
        bool v0 = i0 < end, v1 = i1 < end, v2 = i2 < end, v3 = i3 < end;
        int s0 = v0 ? g_col[i0] : node;
        int s1 = v1 ? g_col[i1] : node;
        int s2 = v2 ? g_col[i2] : node;
        int s3 = v3 ? g_col[i3] : node;
        float4 x0 = *(const float4*)(g_xl + s0 * DD + hq * 4);
        float4 x1 = *(const float4*)(g_xl + s1 * DD + hq * 4);
        float4 x2 = *(const float4*)(g_xl + s2 * DD + hq * 4);
        float4 x3 = *(const float4*)(g_xl + s3 * DD + hq * 4);
        float p0 = v0 ? dl4(x0, r, a) : NEG_INF;
        float p1 = v1 ? dl4(x1, r, a) : NEG_INF;
        float p2 = v2 ? dl4(x2, r, a) : NEG_INF;
        float p3 = v3 ? dl4(x3, r, a) : NEG_INF;
        // quad sums (full score on every lane of the head's quad group)
        p0 += __shfl_xor_sync(0xffffffffu, p0, 1); p0 += __shfl_xor_sync(0xffffffffu, p0, 2);
        p1 += __shfl_xor_sync(0xffffffffu, p1, 1); p1 += __shfl_xor_sync(0xffffffffu, p1, 2);
        p2 += __shfl_xor_sync(0xffffffffu, p2, 1); p2 += __shfl_xor_sync(0xffffffffu, p2, 2);
        p3 += __shfl_xor_sync(0xffffffffu, p3, 1); p3 += __shfl_xor_sync(0xffffffffu, p3, 2);
        // one max update per batch of 8 edges
        float lm = fmaxf(fmaxf(p0, p1), fmaxf(p2, p3));
        float bm = fmaxf(lm, __shfl_xor_sync(0xffffffffu, lm, 16));
        if (bm > m) {
            float f = __expf(m - bm);
            s *= f; c.x *= f; c.y *= f; c.z *= f; c.w *= f;
            m = bm;
        }
        float w0 = __expf(p0 - m), w1 = __expf(p1 - m);
        float w2 = __expf(p2 - m), w3 = __expf(p3 - m);
        s += (w0 + w1) + (w2 + w3);
        c.x += w0 * x0.x; c.y += w0 * x0.y; c.z += w0 * x0.z; c.w += w0 * x0.w;
        c.x += w1 * x1.x; c.y += w1 * x1.y; c.z += w1 * x1.z; c.w += w1 * x1.w;
        c.x += w2 * x2.x; c.y += w2 * x2.y; c.z += w2 * x2.z; c.w += w2 * x2.w;
        c.x += w3 * x3.x; c.y += w3 * x3.y; c.z += w3 * x3.z; c.w += w3 * x3.w;
    }
    s   += __shfl_xor_sync(0xffffffffu, s, 16);
    c.x += __shfl_xor_sync(0xffffffffu, c.x, 16);
    c.y += __shfl_xor_sync(0xffffffffu, c.y, 16);
    c.z += __shfl_xor_sync(0xffffffffu, c.z, 16);
    c.w += __shfl_xor_sync(0xffffffffu, c.w, 16);
    float inv = 1.f / (s + 1e-16f);

    if (eg == 0) {
        *(float4*)&sout[wib][hq * 4] =
            make_float4(c.x * inv, c.y * inv, c.z * inv, c.w * inv);
    }
    __syncwarp();

    float alpha = *alpha_p;
    int cch = lane * 2;
    float t0 = sout[wib][cch]     + g_res[node * DD + cch];
    float t1 = sout[wib][cch + 1] + g_res[node * DD + cch + 1];
    t0 = alpha * t0 + (1.f - alpha) * g_h0[node * DD + cch];
    t1 = alpha * t1 + (1.f - alpha) * g_h0[node * DD + cch + 1];
    float sum = t0 + t1;
    #pragma unroll
    for (int o = 1; o < 32; o <<= 1) sum += __shfl_xor_sync(0xffffffffu, sum, o);
    float mean = sum * (1.f / 64.f);
    float d0 = t0 - mean, d1 = t1 - mean;
    float vs = d0 * d0 + d1 * d1;
    #pragma unroll
    for (int o = 1; o < 32; o <<= 1) vs += __shfl_xor_sync(0xffffffffu, vs, o);
    float rstd = rsqrtf(vs * (1.f / 64.f) + 1e-5f);
    float h0v = gamma[cch]     * d0 * rstd + beta[cch];
    float h1v = gamma[cch + 1] * d1 * rstd + beta[cch + 1];

    if (!LAST) {
        g_h[node * DD + cch]     = h0v;
        g_h[node * DD + cch + 1] = h1v;
    } else {
        sout[wib][cch]     = h0v;
        sout[wib][cch + 1] = h1v;
        __syncwarp();
        float z = b1[lane];
        #pragma unroll
        for (int k = 0; k < DD; k++) z += sout[wib][k] * W1[k * 32 + lane];
        z = fmaxf(z, 0.f);
        float ps = z * W2[lane];
        #pragma unroll
        for (int o = 1; o < 32; o <<= 1) ps += __shfl_xor_sync(0xffffffffu, ps, o);
        if (lane == 0) out[node] = 1.f / (1.f + __expf(-(ps + b2[0])));
    }
}

// ---------------- launch ----------------
extern "C" void kernel_launch(void* const* d_in, const int* in_sizes, int n_in,
                              void* d_out, int out_size) {
    const float* x         = (const float*)d_in[0];
    const int*   node_type = (const int*)d_in[1];
    const int*   esrc      = (const int*)d_in[2];
    const int*   edst      = (const int*)d_in[3];
    const float* Wt        = (const float*)d_in[4];
    const float* bt        = (const float*)d_in[5];
    const float* Et        = (const float*)d_in[6];
    const float* Wp        = (const float*)d_in[7];
    const float* bp        = (const float*)d_in[8];
    const float* Wl        = (const float*)d_in[9];
    const float* bl        = (const float*)d_in[10];
    const float* Wr        = (const float*)d_in[11];
    const float* br        = (const float*)d_in[12];
    const float* att       = (const float*)d_in[13];
    const float* Wres      = (const float*)d_in[14];
    const float* bconv     = (const float*)d_in[15];
    const float* gamma     = (const float*)d_in[16];
    const float* beta      = (const float*)d_in[17];
    const float* alpha     = (const float*)d_in[18];
    const float* W1        = (const float*)d_in[19];
    const float* b1        = (const float*)d_in[20];
    const float* W2        = (const float*)d_in[21];
    const float* b2        = (const float*)d_in[22];
    float* out = (float*)d_out;

    k_csr<<<CSRB, CSRT>>>(esrc, edst);                                   // 0
    k_input<<<(NN + 3) / 4, 256>>>(x, node_type, Wt, bt, Et, Wp, bp);    // 1

    for (int l = 0; l < LL; l++) {
        k_gemm3<<<(NN + 63) / 64, GTB>>>(Wl + l * DD * DD, bl + l * DD,  // 2,4,6
                                         Wr + l * DD * DD, br + l * DD,
                                         Wres + l * DD * DD, bconv + l * DD);
        if (l < LL - 1)
            k_gat<false><<<(NN + 7) / 8, 256>>>(att + l * HH * CC,       // 3,5
                gamma + l * DD, beta + l * DD, alpha,
                nullptr, nullptr, nullptr, nullptr, nullptr);
        else
            k_gat<true><<<(NN + 7) / 8, 256>>>(att + l * HH * CC,       // 7
                gamma + l * DD, beta + l * DD, alpha,
                W1, b1, W2, b2, out);
    }
}